// round 12
// baseline (speedup 1.0000x reference)
#include <cuda_runtime.h>
#include <math.h>

#define NN 50000
#define EE 800000
#define DD 128
#define HH 32
#define JP (HH / 2)          // 16 j-pairs per matrix

#define FT 256               // threads per block (fused kernel)
#define GB 888               // fused grid: <= 6 blocks/SM x 152 SMs (GB300) = 912 slots
#define NCH 196              // ceil(NN / 256) scan chunks

// ---------------- scratch (__device__ globals; no allocation) ----------------
__device__ int   g_deg[NN];          // zero-initialized; re-zeroed at end of each run
__device__ int   g_off[NN];
__device__ int   g_fill[NN];
__device__ int   g_srcs[EE];         // src node per CSR slot (grouped by dst)
__device__ int   g_part[NCH];
__device__ float g_y[NN * HH];       // x @ W1_l^T
__device__ float g_r[NN * HH];       // x @ W1_r^T
__device__ float g_s[NN];            // h . W2_l
__device__ float g_t[NN];            // h . W2_r
__device__ int   g_bar_count;        // grid barrier arrivals (returns to 0 each barrier)
__device__ volatile int g_bar_sense; // last completed phase (stale across runs OK: waiters spin while != phase)

// ---------------- packed f32x2 helpers ----------------
__device__ __forceinline__ void fma2(unsigned long long& d,
                                     unsigned long long a,
                                     unsigned long long b) {
    asm("fma.rn.f32x2 %0, %1, %2, %0;" : "+l"(d) : "l"(a), "l"(b));
}
__device__ __forceinline__ unsigned long long bcast2(float v) {
    unsigned long long r;
    unsigned int u = __float_as_uint(v);
    asm("mov.b64 %0, {%1, %1};" : "=l"(r) : "r"(u));
    return r;
}
__device__ __forceinline__ unsigned long long pack2(float lo, float hi) {
    unsigned long long r;
    asm("mov.b64 %0, {%1, %2};" : "=l"(r) : "r"(__float_as_uint(lo)), "r"(__float_as_uint(hi)));
    return r;
}
__device__ __forceinline__ float lo2(unsigned long long v) {
    return __uint_as_float((unsigned int)(v & 0xFFFFFFFFull));
}
__device__ __forceinline__ float hi2(unsigned long long v) {
    return __uint_as_float((unsigned int)(v >> 32));
}

// ---------------- per-block dtype sniff for edge_index ----------------
// int64 indices all < 50000 -> high u32 of each u64 word always 0.
// int32 layout packs two indices per u64 -> some high u32 nonzero (whp).
// Same 2KB read by every block -> L2-broadcast, effectively free.
__device__ __forceinline__ int sniff_mode32(const void* ei, int tid) {
    __shared__ int s_flag;
    if (tid == 0) s_flag = 0;
    __syncthreads();
    if (tid < 256) {
        unsigned long long v = ((const unsigned long long*)ei)[tid];
        if (v > 0xFFFFFFFFull) atomicOr(&s_flag, 1);
    }
    __syncthreads();
    return s_flag;
}

__device__ __forceinline__ int load_idx(const void* ei, int mode32, int row, int e) {
    if (mode32) return ((const int*)ei)[(size_t)row * EE + e];
    return (int)(((const long long*)ei)[(size_t)row * EE + e]);
}

// ---------------- grid-wide software barrier (sense-based) ----------------
// Safe: GB=888 <= 912 co-resident slots guaranteed by __launch_bounds__(FT, 6);
// grid fits entirely in wave 1, so no block waits on a retired block.
__device__ __forceinline__ void gbar(int phase) {
    __syncthreads();
    if (threadIdx.x == 0) {
        __threadfence();                       // release prior writes
        int t = atomicAdd(&g_bar_count, 1);
        if (t == GB - 1) {
            g_bar_count = 0;
            __threadfence();
            g_bar_sense = phase;
        } else {
            while (g_bar_sense != phase) __nanosleep(64);
        }
        __threadfence();                       // acquire
    }
    __syncthreads();
}

// ---------------- GEMM1: y = x @ W1_l^T, r = x @ W1_r^T (FFMA2 path) --------
// Each block packs raw weights into its own smem (no separate pack kernel).
__global__ void __launch_bounds__(256) k_gemm1(const float* __restrict__ x,
                                               const float* __restrict__ W1l,
                                               const float* __restrict__ W1r) {
    __shared__ unsigned long long sWl[DD * JP];   // 16 KB, [k][jp]
    __shared__ unsigned long long sWr[DD * JP];   // 16 KB
    int tid = threadIdx.x;
    for (int idx = tid; idx < DD * JP; idx += blockDim.x) {
        int k  = idx >> 4;                 // 0..127
        int jp = idx & (JP - 1);           // 0..15
        sWl[idx] = pack2(W1l[(2 * jp + 0) * DD + k], W1l[(2 * jp + 1) * DD + k]);
        sWr[idx] = pack2(W1r[(2 * jp + 0) * DD + k], W1r[(2 * jp + 1) * DD + k]);
    }
    __syncthreads();
    int n = blockIdx.x * blockDim.x + tid;
    if (n >= NN) return;

    unsigned long long accl[JP], accr[JP];
    #pragma unroll
    for (int j = 0; j < JP; j++) { accl[j] = 0ull; accr[j] = 0ull; }

    const float4* xr = (const float4*)(x + (size_t)n * DD);
    #pragma unroll 2
    for (int kk = 0; kk < DD / 4; kk++) {
        float4 xv = xr[kk];
        #pragma unroll
        for (int q = 0; q < 4; q++) {
            float xk = (q == 0) ? xv.x : (q == 1) ? xv.y : (q == 2) ? xv.z : xv.w;
            unsigned long long xx = bcast2(xk);
            int k = kk * 4 + q;
            const ulonglong2* wl2 = (const ulonglong2*)&sWl[k * JP];
            const ulonglong2* wr2 = (const ulonglong2*)&sWr[k * JP];
            #pragma unroll
            for (int p = 0; p < JP / 2; p++) {
                ulonglong2 wl = wl2[p];
                fma2(accl[2 * p + 0], xx, wl.x);
                fma2(accl[2 * p + 1], xx, wl.y);
                ulonglong2 wr = wr2[p];
                fma2(accr[2 * p + 0], xx, wr.x);
                fma2(accr[2 * p + 1], xx, wr.y);
            }
        }
    }
    float4* yo = (float4*)(g_y + (size_t)n * HH);
    float4* ro = (float4*)(g_r + (size_t)n * HH);
    #pragma unroll
    for (int p = 0; p < HH / 4; p++) {
        yo[p] = make_float4(lo2(accl[2*p]), hi2(accl[2*p]), lo2(accl[2*p+1]), hi2(accl[2*p+1]));
        ro[p] = make_float4(lo2(accr[2*p]), hi2(accr[2*p]), lo2(accr[2*p+1]), hi2(accr[2*p+1]));
    }
}

// ---------------- fused persistent kernel: CSR build + both aggregations -----
__global__ void __launch_bounds__(FT, 6) k_fused(
    const void* __restrict__ ei,
    const float* __restrict__ b1,
    const float* __restrict__ W2l,
    const float* __restrict__ W2r,
    const float* __restrict__ b2,
    float* __restrict__ out) {

    __shared__ int sh[FT];
    int tid  = threadIdx.x;
    int bid  = blockIdx.x;
    int gtid = bid * FT + tid;
    const int TT = GB * FT;            // total threads
    int mode = sniff_mode32(ei, tid);

    // ---- Phase A: degree histogram (g_deg zeroed by previous run / initial load)
    #pragma unroll 1
    for (int e = gtid; e < EE; e += TT) {
        int d = load_idx(ei, mode, 1, e);
        atomicAdd(&g_deg[d], 1);
    }
    gbar(1);

    // ---- Phase B1: block-local exclusive scan of 256-chunks
    if (bid < NCH) {
        int i = bid * FT + tid;
        int v = (i < NN) ? g_deg[i] : 0;
        sh[tid] = v;
        __syncthreads();
        #pragma unroll
        for (int off = 1; off < FT; off <<= 1) {
            int add = (tid >= off) ? sh[tid - off] : 0;
            __syncthreads();
            sh[tid] += add;
            __syncthreads();
        }
        if (i < NN) g_off[i] = sh[tid] - v;       // exclusive within chunk
        if (tid == FT - 1) g_part[bid] = sh[tid]; // chunk total
    }
    gbar(2);

    // ---- Phase B2: block 0 scans chunk totals (exclusive)
    if (bid == 0) {
        int v = (tid < NCH) ? g_part[tid] : 0;
        sh[tid] = v;
        __syncthreads();
        #pragma unroll
        for (int off = 1; off < FT; off <<= 1) {
            int add = (tid >= off) ? sh[tid - off] : 0;
            __syncthreads();
            sh[tid] += add;
            __syncthreads();
        }
        if (tid < NCH) g_part[tid] = sh[tid] - v;
    }
    gbar(3);

    // ---- Phase B3: add chunk prefix; init fill cursors
    #pragma unroll 1
    for (int i = gtid; i < NN; i += TT) {
        int o = g_off[i] + __ldg(&g_part[i >> 8]);
        g_off[i] = o;
        g_fill[i] = o;
    }
    gbar(4);

    // ---- Phase C: bucket edges into CSR
    #pragma unroll 1
    for (int e = gtid; e < EE; e += TT) {
        int s = load_idx(ei, mode, 0, e);
        int d = load_idx(ei, mode, 1, e);
        int pos = atomicAdd(&g_fill[d], 1);
        g_srcs[pos] = s;
    }
    gbar(5);

    // ---- Phase D: layer-1 aggregate + ReLU + layer-2 dots (warp per node)
    int wid  = gtid >> 5;
    int lane = tid & 31;
    const int NW = TT / 32;
    float bb = b1[lane];
    float wl = W2l[lane];
    float wr = W2r[lane];
    for (int n = wid; n < NN; n += NW) {
        int beg = __ldg(&g_off[n]);
        int dg  = __ldg(&g_deg[n]);
        float a0 = 0.f, a1 = 0.f, a2 = 0.f, a3 = 0.f;
        int i = 0;
        for (; i + 4 <= dg; i += 4) {
            int s0 = __ldg(&g_srcs[beg + i + 0]);
            int s1 = __ldg(&g_srcs[beg + i + 1]);
            int s2 = __ldg(&g_srcs[beg + i + 2]);
            int s3 = __ldg(&g_srcs[beg + i + 3]);
            a0 += __ldg(&g_y[(size_t)s0 * HH + lane]);
            a1 += __ldg(&g_y[(size_t)s1 * HH + lane]);
            a2 += __ldg(&g_y[(size_t)s2 * HH + lane]);
            a3 += __ldg(&g_y[(size_t)s3 * HH + lane]);
        }
        for (; i < dg; i++) {
            int src = __ldg(&g_srcs[beg + i]);
            a0 += __ldg(&g_y[(size_t)src * HH + lane]);
        }
        float acc = (a0 + a1) + (a2 + a3);
        float inv = 1.f / (float)max(dg, 1);
        float h = acc * inv + bb + __ldg(&g_r[(size_t)n * HH + lane]);
        h = fmaxf(h, 0.f);
        float sl = h * wl;
        float tl = h * wr;
        #pragma unroll
        for (int o = 16; o > 0; o >>= 1) {
            sl += __shfl_xor_sync(0xffffffffu, sl, o);
            tl += __shfl_xor_sync(0xffffffffu, tl, o);
        }
        if (lane == 0) { g_s[n] = sl; g_t[n] = tl; }
    }
    gbar(6);

    // ---- Phase E: layer-2 scalar aggregate + sigmoid; reset g_deg for next run
    float b2v = b2[0];
    for (int n = wid; n < NN; n += NW) {
        int beg = __ldg(&g_off[n]);
        int dg  = __ldg(&g_deg[n]);
        float a0 = 0.f, a1 = 0.f;
        int i = lane;
        for (; i + 32 < dg; i += 64) {
            a0 += __ldg(&g_s[__ldg(&g_srcs[beg + i])]);
            a1 += __ldg(&g_s[__ldg(&g_srcs[beg + i + 32])]);
        }
        if (i < dg) a0 += __ldg(&g_s[__ldg(&g_srcs[beg + i])]);
        float acc = a0 + a1;
        #pragma unroll
        for (int o = 16; o > 0; o >>= 1) acc += __shfl_xor_sync(0xffffffffu, acc, o);
        if (lane == 0) {
            float z = acc / (float)max(dg, 1) + b2v + __ldg(&g_t[n]);
            out[n] = 1.f / (1.f + expf(-z));
            g_deg[n] = 0;                       // cross-replay reset (after last read)
        }
    }
}

// ---------------- launch: 2 kernels total ----------------
extern "C" void kernel_launch(void* const* d_in, const int* in_sizes, int n_in,
                              void* d_out, int out_size) {
    const float* x   = (const float*)d_in[0];
    const void*  ei  = d_in[1];               // int64 or int32, sniffed on device
    const float* W1l = (const float*)d_in[2];
    const float* b1  = (const float*)d_in[3];
    const float* W1r = (const float*)d_in[4];
    const float* W2l = (const float*)d_in[5];
    const float* b2  = (const float*)d_in[6];
    const float* W2r = (const float*)d_in[7];
    float* out = (float*)d_out;

    k_gemm1<<<(NN + 255) / 256, 256>>>(x, W1l, W1r);
    k_fused<<<GB, FT>>>(ei, b1, W2l, W2r, b2, out);
}